// round 2
// baseline (speedup 1.0000x reference)
#include <cuda_runtime.h>

#define BB 16
#define NN 1024
#define DD 128
#define BN (BB*NN)

// scratch (device globals: allocation-free per harness rules)
__device__ float g_h[BN*DD];                    // 8 MB
__device__ float g_t[BN*DD];                    // 8 MB
__device__ float g_P[(size_t)BB*NN*NN];         // 64 MB: exp(scores), masked = -1.0
__device__ float g_rden[BB*NN];                 // 64 KB: 1/column-sum

// ---------------------------------------------------------------------------
// 8x8 micro-tile FMA step over 4 k-values.
// As: [rows][LDA] row-major (k contiguous), Bs: [k][LDB] (cols contiguous)
// ---------------------------------------------------------------------------
template<int LDA, int LDB>
__device__ __forceinline__ void mm8x8x4(const float* As, const float* Bs,
                                        int r0, int c0, int l, float acc[8][8]) {
    float a[8][4];
    float bb[4][8];
#pragma unroll
    for (int i = 0; i < 8; i++) {
        float4 v = *(const float4*)&As[(r0 + i) * LDA + l];
        a[i][0] = v.x; a[i][1] = v.y; a[i][2] = v.z; a[i][3] = v.w;
    }
#pragma unroll
    for (int q = 0; q < 4; q++) {
        float4 v0 = *(const float4*)&Bs[(l + q) * LDB + c0];
        float4 v1 = *(const float4*)&Bs[(l + q) * LDB + c0 + 4];
        bb[q][0] = v0.x; bb[q][1] = v0.y; bb[q][2] = v0.z; bb[q][3] = v0.w;
        bb[q][4] = v1.x; bb[q][5] = v1.y; bb[q][6] = v1.z; bb[q][7] = v1.w;
    }
#pragma unroll
    for (int q = 0; q < 4; q++)
#pragma unroll
        for (int i = 0; i < 8; i++)
#pragma unroll
            for (int j = 0; j < 8; j++)
                acc[i][j] += a[i][q] * bb[q][j];
}

// ---------------------------------------------------------------------------
// K1/K2: C[m][c] = sum_k A[m][k] * (BTRANS ? Bm[c][k] : Bm[k][c]) (+ bias[c])
// M blocked by 128 rows; K = Ncols = 128.
// ---------------------------------------------------------------------------
template<bool BTRANS, bool BIAS>
__global__ void __launch_bounds__(256, 1)
gemm128_kernel(const float* __restrict__ Am, const float* __restrict__ Bm,
               const float* __restrict__ bias, float* __restrict__ Cm) {
    extern __shared__ float smem[];
    float* As = smem;              // [128][128]
    float* Bs = smem + 128 * 128;  // [128][128], layout Bs[k][c]
    const int tid = threadIdx.x;
    const int m0 = blockIdx.x * 128;

    const float4* Ag = (const float4*)(Am + (size_t)m0 * 128);
#pragma unroll
    for (int it = 0; it < 16; it++)
        ((float4*)As)[tid + it * 256] = Ag[tid + it * 256];

    if (BTRANS) {
        // Bs[k][c] = Bm[c][k]: transposed read (L2-absorbed), conflict-free STS
#pragma unroll
        for (int it = 0; it < 16; it++) {
            int lin = tid + it * 256;
            int c = lin & 127, k4 = lin >> 7;
            float4 v = ((const float4*)Bm)[c * 32 + k4];
            Bs[(4 * k4 + 0) * 128 + c] = v.x;
            Bs[(4 * k4 + 1) * 128 + c] = v.y;
            Bs[(4 * k4 + 2) * 128 + c] = v.z;
            Bs[(4 * k4 + 3) * 128 + c] = v.w;
        }
    } else {
#pragma unroll
        for (int it = 0; it < 16; it++)
            ((float4*)Bs)[tid + it * 256] = ((const float4*)Bm)[tid + it * 256];
    }
    __syncthreads();

    const int r0 = (tid >> 4) * 8, c0 = (tid & 15) * 8;
    float acc[8][8] = {};
#pragma unroll
    for (int l = 0; l < 128; l += 4)
        mm8x8x4<128, 128>(As, Bs, r0, c0, l, acc);

    float bv[8];
#pragma unroll
    for (int j = 0; j < 8; j++) bv[j] = BIAS ? bias[c0 + j] : 0.f;
#pragma unroll
    for (int i = 0; i < 8; i++) {
        float4 o0, o1;
        o0.x = acc[i][0] + bv[0]; o0.y = acc[i][1] + bv[1];
        o0.z = acc[i][2] + bv[2]; o0.w = acc[i][3] + bv[3];
        o1.x = acc[i][4] + bv[4]; o1.y = acc[i][5] + bv[5];
        o1.z = acc[i][6] + bv[6]; o1.w = acc[i][7] + bv[7];
        *(float4*)&Cm[(size_t)(m0 + r0 + i) * 128 + c0]     = o0;
        *(float4*)&Cm[(size_t)(m0 + r0 + i) * 128 + c0 + 4] = o1;
    }
}

// ---------------------------------------------------------------------------
// K3: e[j,k] = sum_l t[j,l]h[k,l] + t[k,l]h[j,l]  (symmetric)
// P = adj>0 ? exp(e) : -1.0    (sign bit = mask, |P| feeds denominator)
// One block per (b, tile pair jT<=kT); mirrored tile written via smem transpose.
// ---------------------------------------------------------------------------
__global__ void __launch_bounds__(256, 1)
scores_kernel(const float* __restrict__ adj) {
    extern __shared__ float smem[];
    float* A1s = smem;           // t_j  [128][64]
    float* A2s = smem + 8192;    // h_j  [128][64]
    float* B1s = smem + 16384;   // h_k^T [64][128]
    float* B2s = smem + 24576;   // t_k^T [64][128]

    const int b = blockIdx.y;
    int p = blockIdx.x, jT = 0;
    while (p >= 8 - jT) { p -= 8 - jT; jT++; }
    const int kT = jT + p;

    const float* tb = g_t + (size_t)b * NN * DD;
    const float* hb = g_h + (size_t)b * NN * DD;
    const int tid = threadIdx.x;
    const int r0 = (tid >> 4) * 8, c0 = (tid & 15) * 8;
    float acc[8][8] = {};

#pragma unroll
    for (int l0 = 0; l0 < 128; l0 += 64) {
        if (l0) __syncthreads();
#pragma unroll
        for (int it = 0; it < 8; it++) {
            int lin = tid + it * 256;               // 2048 float4 per array
            int row = lin >> 4, l4 = lin & 15;
            ((float4*)A1s)[lin] = *(const float4*)&tb[(size_t)(jT * 128 + row) * DD + l0 + 4 * l4];
            ((float4*)A2s)[lin] = *(const float4*)&hb[(size_t)(jT * 128 + row) * DD + l0 + 4 * l4];
            int k = lin & 127, l4b = lin >> 7;      // transpose fill: conflict-free STS
            float4 v1 = *(const float4*)&hb[(size_t)(kT * 128 + k) * DD + l0 + 4 * l4b];
            float4 v2 = *(const float4*)&tb[(size_t)(kT * 128 + k) * DD + l0 + 4 * l4b];
            B1s[(4 * l4b + 0) * 128 + k] = v1.x;
            B1s[(4 * l4b + 1) * 128 + k] = v1.y;
            B1s[(4 * l4b + 2) * 128 + k] = v1.z;
            B1s[(4 * l4b + 3) * 128 + k] = v1.w;
            B2s[(4 * l4b + 0) * 128 + k] = v2.x;
            B2s[(4 * l4b + 1) * 128 + k] = v2.y;
            B2s[(4 * l4b + 2) * 128 + k] = v2.z;
            B2s[(4 * l4b + 3) * 128 + k] = v2.w;
        }
        __syncthreads();
#pragma unroll
        for (int l = 0; l < 64; l += 4) {
            mm8x8x4<64, 128>(A1s, B1s, r0, c0, l, acc);   // t_j . h_k
            mm8x8x4<64, 128>(A2s, B2s, r0, c0, l, acc);   // h_j . t_k
        }
    }

    const float* adjb = adj + (size_t)b * NN * NN;
    float* Pb = g_P + (size_t)b * NN * NN;

    // direct tile (jT, kT)
#pragma unroll
    for (int i = 0; i < 8; i++) {
        int jg = jT * 128 + r0 + i;
#pragma unroll
        for (int g = 0; g < 2; g++) {
            int kg = kT * 128 + c0 + 4 * g;
            float4 av = *(const float4*)&adjb[(size_t)jg * NN + kg];
            float4 pv;
            pv.x = (av.x > 0.f) ? __expf(acc[i][4 * g + 0]) : -1.f;
            pv.y = (av.y > 0.f) ? __expf(acc[i][4 * g + 1]) : -1.f;
            pv.z = (av.z > 0.f) ? __expf(acc[i][4 * g + 2]) : -1.f;
            pv.w = (av.w > 0.f) ? __expf(acc[i][4 * g + 3]) : -1.f;
            *(float4*)&Pb[(size_t)jg * NN + kg] = pv;
        }
    }

    // mirrored tile (kT, jT) via smem transpose (e is symmetric)
    if (jT != kT) {
        __syncthreads();
        float* Ts = smem;  // [128][129]
#pragma unroll
        for (int i = 0; i < 8; i++)
#pragma unroll
            for (int j = 0; j < 8; j++)
                Ts[(c0 + j) * 129 + (r0 + i)] = acc[i][j];
        __syncthreads();
#pragma unroll
        for (int it = 0; it < 16; it++) {
            int lin = tid + it * 256;          // 4096 float4
            int rr = lin >> 5, c4 = lin & 31;
            int kg = kT * 128 + rr;
            int jgc = jT * 128 + 4 * c4;
            float4 av = *(const float4*)&adjb[(size_t)kg * NN + jgc];
            const float* tr = &Ts[rr * 129 + 4 * c4];
            float4 pv;
            pv.x = (av.x > 0.f) ? __expf(tr[0]) : -1.f;
            pv.y = (av.y > 0.f) ? __expf(tr[1]) : -1.f;
            pv.z = (av.z > 0.f) ? __expf(tr[2]) : -1.f;
            pv.w = (av.w > 0.f) ? __expf(tr[3]) : -1.f;
            *(float4*)&Pb[(size_t)kg * NN + jgc] = pv;
        }
    }
}

// ---------------------------------------------------------------------------
// K4: rden[b,k] = 1 / sum_j |P[b,j,k]|   (deterministic two-level reduce)
// ---------------------------------------------------------------------------
__global__ void den_kernel() {
    __shared__ float red[512];
    const int b = blockIdx.y;
    const int tid = threadIdx.x;
    const int k = blockIdx.x * 128 + (tid & 127);
    const int seg = tid >> 7;  // 0..3
    const float* Pb = g_P + (size_t)b * NN * NN + k;
    float s = 0.f;
#pragma unroll 4
    for (int j = seg * 256; j < seg * 256 + 256; j++)
        s += fabsf(Pb[(size_t)j * NN]);
    red[tid] = s;
    __syncthreads();
    if (tid < 128) {
        float tot = red[tid] + red[tid + 128] + red[tid + 256] + red[tid + 384];
        g_rden[b * NN + k] = 1.0f / tot;
    }
}

// ---------------------------------------------------------------------------
// K5: h' = relu(attn @ h), attn[i,j] = max(P[i,j],0) * rden[j]; fused gates:
// out = sigm(h'.wou+x.wox) * tanh(sigm(h'.wiu+x.wix)*h' + sigm(h'.wfu+x.wfx)*x)
// Block = 128 i-rows x all 128 d-cols -> gates reduce entirely in-block.
// ---------------------------------------------------------------------------
__global__ void __launch_bounds__(256, 1)
agg_kernel(const float* __restrict__ x,
           const float* __restrict__ wiu, const float* __restrict__ wix,
           const float* __restrict__ wfu, const float* __restrict__ wfx,
           const float* __restrict__ wou, const float* __restrict__ wox,
           float* __restrict__ out) {
    extern __shared__ float smem[];
    float* As = smem;         // [128][32] attention chunk
    float* Bs = smem + 4096;  // [32][128] h chunk
    const int b = blockIdx.y;
    const int i0 = blockIdx.x * 128;
    const int tid = threadIdx.x;
    const int r0 = (tid >> 4) * 8, c0 = (tid & 15) * 8;
    float acc[8][8] = {};

    for (int j0 = 0; j0 < NN; j0 += 32) {
        if (j0) __syncthreads();
#pragma unroll
        for (int it = 0; it < 4; it++) {
            int lin = tid + it * 256;           // 1024 float4 per array
            int i = lin >> 3, j4 = lin & 7;
            float4 pv = *(const float4*)&g_P[((size_t)b * NN + i0 + i) * NN + j0 + 4 * j4];
            float4 rd = *(const float4*)&g_rden[b * NN + j0 + 4 * j4];
            float4 v;
            v.x = fmaxf(pv.x, 0.f) * rd.x;
            v.y = fmaxf(pv.y, 0.f) * rd.y;
            v.z = fmaxf(pv.z, 0.f) * rd.z;
            v.w = fmaxf(pv.w, 0.f) * rd.w;
            ((float4*)As)[lin] = v;
            int jp = lin >> 5, d4 = lin & 31;
            ((float4*)Bs)[lin] = *(const float4*)&g_h[((size_t)b * NN + j0 + jp) * DD + 4 * d4];
        }
        __syncthreads();
#pragma unroll
        for (int l = 0; l < 32; l += 4)
            mm8x8x4<32, 128>(As, Bs, r0, c0, l, acc);
    }

    // stage h' (relu) into smem, then fused gate epilogue
    __syncthreads();
    float* hp = smem;  // [128][128]
#pragma unroll
    for (int i = 0; i < 8; i++)
#pragma unroll
        for (int j = 0; j < 8; j++)
            hp[(r0 + i) * 128 + c0 + j] = fmaxf(acc[i][j], 0.f);
    __syncthreads();

    const int warp = tid >> 5, lane = tid & 31;
    float4 ui = *(const float4*)&wiu[lane * 4];
    float4 xi = *(const float4*)&wix[lane * 4];
    float4 uf = *(const float4*)&wfu[lane * 4];
    float4 xf = *(const float4*)&wfx[lane * 4];
    float4 uo = *(const float4*)&wou[lane * 4];
    float4 xo = *(const float4*)&wox[lane * 4];

    for (int r = warp; r < 128; r += 8) {
        size_t n = (size_t)b * NN + i0 + r;
        float4 h4 = *(const float4*)&hp[r * 128 + lane * 4];
        float4 x4 = *(const float4*)&x[n * DD + lane * 4];
        float zi = h4.x * ui.x + h4.y * ui.y + h4.z * ui.z + h4.w * ui.w
                 + x4.x * xi.x + x4.y * xi.y + x4.z * xi.z + x4.w * xi.w;
        float zf = h4.x * uf.x + h4.y * uf.y + h4.z * uf.z + h4.w * uf.w
                 + x4.x * xf.x + x4.y * xf.y + x4.z * xf.z + x4.w * xf.w;
        float zo = h4.x * uo.x + h4.y * uo.y + h4.z * uo.z + h4.w * uo.w
                 + x4.x * xo.x + x4.y * xo.y + x4.z * xo.z + x4.w * xo.w;
#pragma unroll
        for (int off = 16; off; off >>= 1) {
            zi += __shfl_xor_sync(0xffffffffu, zi, off);
            zf += __shfl_xor_sync(0xffffffffu, zf, off);
            zo += __shfl_xor_sync(0xffffffffu, zo, off);
        }
        float ic = 1.f / (1.f + expf(-zi));
        float fc = 1.f / (1.f + expf(-zf));
        float oc = 1.f / (1.f + expf(-zo));
        float4 o;
        o.x = oc * tanhf(ic * h4.x + fc * x4.x);
        o.y = oc * tanhf(ic * h4.y + fc * x4.y);
        o.z = oc * tanhf(ic * h4.z + fc * x4.z);
        o.w = oc * tanhf(ic * h4.w + fc * x4.w);
        *(float4*)&out[n * DD + lane * 4] = o;
    }
}

// ---------------------------------------------------------------------------
extern "C" void kernel_launch(void* const* d_in, const int* in_sizes, int n_in,
                              void* d_out, int out_size) {
    const float* x   = (const float*)d_in[0];
    const float* adj = (const float*)d_in[1];
    const float* Ww  = (const float*)d_in[2];
    const float* Wb  = (const float*)d_in[3];
    const float* A   = (const float*)d_in[4];
    const float* wiu = (const float*)d_in[5];
    const float* wix = (const float*)d_in[6];
    const float* wfu = (const float*)d_in[7];
    const float* wfx = (const float*)d_in[8];
    const float* wou = (const float*)d_in[9];
    const float* wox = (const float*)d_in[10];
    float* out = (float*)d_out;

    float *hptr, *tptr;
    cudaGetSymbolAddress((void**)&hptr, g_h);
    cudaGetSymbolAddress((void**)&tptr, g_t);

    cudaFuncSetAttribute((const void*)gemm128_kernel<true, true>,
                         cudaFuncAttributeMaxDynamicSharedMemorySize, 131072);
    cudaFuncSetAttribute((const void*)gemm128_kernel<false, false>,
                         cudaFuncAttributeMaxDynamicSharedMemorySize, 131072);
    cudaFuncSetAttribute((const void*)scores_kernel,
                         cudaFuncAttributeMaxDynamicSharedMemorySize, 131072);
    cudaFuncSetAttribute((const void*)agg_kernel,
                         cudaFuncAttributeMaxDynamicSharedMemorySize, 65536);

    // K1: h = x @ Ww^T + Wb
    gemm128_kernel<true, true><<<128, 256, 131072>>>(x, Ww, Wb, hptr);
    // K2: t = h @ A
    gemm128_kernel<false, false><<<128, 256, 131072>>>(hptr, A, nullptr, tptr);
    // K3: P = masked exp(scores), pair-tiled symmetric
    scores_kernel<<<dim3(36, 16), 256, 131072>>>(adj);
    // K4: column denominators
    den_kernel<<<dim3(8, 16), 512>>>();
    // K5: aggregation + fused LSTM gates
    agg_kernel<<<dim3(8, 16), 256, 65536>>>(x, wiu, wix, wfu, wfx, wou, wox, out);
}

// round 4
// speedup vs baseline: 1.9264x; 1.9264x over previous
#include <cuda_runtime.h>
#include <cuda_bf16.h>
#include <cstdint>

#define BB 16
#define NN 1024
#define DD 128
#define BN (BB*NN)

// ---------------- scratch (device globals) ----------------
__device__ float         g_h[BN*DD];                   // 8 MB fp32
__device__ float         g_t[BN*DD];                   // 8 MB fp32
__device__ __nv_bfloat16 g_u1[(size_t)BN*256];         // 8 MB  [t|h] hi
__device__ __nv_bfloat16 g_u2[(size_t)BN*256];         // 8 MB  [t|h] lo
__device__ __nv_bfloat16 g_v1[(size_t)BN*256];         // 8 MB  [h|t] hi
__device__ __nv_bfloat16 g_v2[(size_t)BN*256];         // 8 MB  [h|t] lo
__device__ __nv_bfloat16 g_hT1[(size_t)BB*DD*NN];      // 4 MB  hT[b][d][j] hi
__device__ __nv_bfloat16 g_hT2[(size_t)BB*DD*NN];      // 4 MB  lo
__device__ float         g_P[(size_t)BB*NN*NN];        // 64 MB exp(scores), masked=-1
__device__ float         g_dpart[BB*8*NN];             // 512 KB
__device__ float         g_rden[BB*NN];                // 64 KB

// ---------------- mma helpers ----------------
__device__ __forceinline__ uint32_t smem_u32(const void* p) {
    uint32_t a;
    asm("{ .reg .u64 t; cvta.to.shared.u64 t, %1; cvt.u32.u64 %0, t; }" : "=r"(a) : "l"(p));
    return a;
}
__device__ __forceinline__ void ldsm4(uint32_t* r, uint32_t addr) {
    asm volatile("ldmatrix.sync.aligned.m8n8.x4.shared.b16 {%0,%1,%2,%3}, [%4];"
                 : "=r"(r[0]), "=r"(r[1]), "=r"(r[2]), "=r"(r[3]) : "r"(addr));
}
__device__ __forceinline__ void mma16816(float* c, const uint32_t* a, const uint32_t* b) {
    asm volatile("mma.sync.aligned.m16n8k16.row.col.f32.bf16.bf16.f32 "
                 "{%0,%1,%2,%3}, {%4,%5,%6,%7}, {%8,%9}, {%0,%1,%2,%3};"
                 : "+f"(c[0]), "+f"(c[1]), "+f"(c[2]), "+f"(c[3])
                 : "r"(a[0]), "r"(a[1]), "r"(a[2]), "r"(a[3]), "r"(b[0]), "r"(b[1]));
}

#define LDO 72            // bf16 elems per smem row (64 data + 8 pad)
#define MATB (128*LDO*2)  // bytes per staged 128x64 matrix = 18432

// ---------------------------------------------------------------------------
// fp32 SIMT 128x128x128 GEMM (K1, K2) — known-good from round 2
// ---------------------------------------------------------------------------
template<int LDA, int LDB>
__device__ __forceinline__ void mm8x8x4(const float* As, const float* Bs,
                                        int r0, int c0, int l, float acc[8][8]) {
    float a[8][4], bb[4][8];
#pragma unroll
    for (int i = 0; i < 8; i++) {
        float4 v = *(const float4*)&As[(r0 + i) * LDA + l];
        a[i][0]=v.x; a[i][1]=v.y; a[i][2]=v.z; a[i][3]=v.w;
    }
#pragma unroll
    for (int q = 0; q < 4; q++) {
        float4 v0 = *(const float4*)&Bs[(l + q) * LDB + c0];
        float4 v1 = *(const float4*)&Bs[(l + q) * LDB + c0 + 4];
        bb[q][0]=v0.x; bb[q][1]=v0.y; bb[q][2]=v0.z; bb[q][3]=v0.w;
        bb[q][4]=v1.x; bb[q][5]=v1.y; bb[q][6]=v1.z; bb[q][7]=v1.w;
    }
#pragma unroll
    for (int q = 0; q < 4; q++)
#pragma unroll
        for (int i = 0; i < 8; i++)
#pragma unroll
            for (int j = 0; j < 8; j++)
                acc[i][j] += a[i][q] * bb[q][j];
}

template<bool BTRANS, bool BIAS>
__global__ void __launch_bounds__(256, 1)
gemm128_kernel(const float* __restrict__ Am, const float* __restrict__ Bm,
               const float* __restrict__ bias, float* __restrict__ Cm) {
    extern __shared__ float smemf[];
    float* As = smemf;
    float* Bs = smemf + 128 * 128;
    const int tid = threadIdx.x;
    const int m0 = blockIdx.x * 128;
    const float4* Ag = (const float4*)(Am + (size_t)m0 * 128);
#pragma unroll
    for (int it = 0; it < 16; it++)
        ((float4*)As)[tid + it * 256] = Ag[tid + it * 256];
    if (BTRANS) {
#pragma unroll
        for (int it = 0; it < 16; it++) {
            int lin = tid + it * 256;
            int c = lin & 127, k4 = lin >> 7;
            float4 v = ((const float4*)Bm)[c * 32 + k4];
            Bs[(4*k4+0)*128+c]=v.x; Bs[(4*k4+1)*128+c]=v.y;
            Bs[(4*k4+2)*128+c]=v.z; Bs[(4*k4+3)*128+c]=v.w;
        }
    } else {
#pragma unroll
        for (int it = 0; it < 16; it++)
            ((float4*)Bs)[tid + it * 256] = ((const float4*)Bm)[tid + it * 256];
    }
    __syncthreads();
    const int r0 = (tid >> 4) * 8, c0 = (tid & 15) * 8;
    float acc[8][8] = {};
#pragma unroll
    for (int l = 0; l < 128; l += 4)
        mm8x8x4<128, 128>(As, Bs, r0, c0, l, acc);
    float bv[8];
#pragma unroll
    for (int j = 0; j < 8; j++) bv[j] = BIAS ? bias[c0 + j] : 0.f;
#pragma unroll
    for (int i = 0; i < 8; i++) {
        float4 o0, o1;
        o0.x=acc[i][0]+bv[0]; o0.y=acc[i][1]+bv[1]; o0.z=acc[i][2]+bv[2]; o0.w=acc[i][3]+bv[3];
        o1.x=acc[i][4]+bv[4]; o1.y=acc[i][5]+bv[5]; o1.z=acc[i][6]+bv[6]; o1.w=acc[i][7]+bv[7];
        *(float4*)&Cm[(size_t)(m0+r0+i)*128 + c0]     = o0;
        *(float4*)&Cm[(size_t)(m0+r0+i)*128 + c0 + 4] = o1;
    }
}

// ---------------------------------------------------------------------------
// prep: u=[t|h], v=[h|t] bf16 hi/lo splits, node-major K=256
// ---------------------------------------------------------------------------
__global__ void prep_split_kernel() {
    int idx4 = blockIdx.x * 256 + threadIdx.x;   // BN*32 float4 groups
    int node = idx4 >> 5, f = (idx4 & 31) * 4;
    float4 tv = *(const float4*)&g_t[(size_t)node * 128 + f];
    float4 hv = *(const float4*)&g_h[(size_t)node * 128 + f];
    float tf[4] = {tv.x, tv.y, tv.z, tv.w};
    float hf[4] = {hv.x, hv.y, hv.z, hv.w};
    __nv_bfloat16 t1[4], t2[4], h1[4], h2[4];
#pragma unroll
    for (int i = 0; i < 4; i++) {
        t1[i] = __float2bfloat16_rn(tf[i]);
        t2[i] = __float2bfloat16_rn(tf[i] - __bfloat162float(t1[i]));
        h1[i] = __float2bfloat16_rn(hf[i]);
        h2[i] = __float2bfloat16_rn(hf[i] - __bfloat162float(h1[i]));
    }
    size_t base = (size_t)node * 256 + f;
    *(uint2*)&g_u1[base]       = *(uint2*)t1;
    *(uint2*)&g_u1[base + 128] = *(uint2*)h1;
    *(uint2*)&g_u2[base]       = *(uint2*)t2;
    *(uint2*)&g_u2[base + 128] = *(uint2*)h2;
    *(uint2*)&g_v1[base]       = *(uint2*)h1;
    *(uint2*)&g_v1[base + 128] = *(uint2*)t1;
    *(uint2*)&g_v2[base]       = *(uint2*)h2;
    *(uint2*)&g_v2[base + 128] = *(uint2*)t2;
}

// prep: hT[b][d][j] bf16 splits
__global__ void prep_hT_kernel() {
    __shared__ float s[32][33];
    const int b = blockIdx.y;
    const int jt = blockIdx.x >> 2, dt = blockIdx.x & 3;
    const int j0 = jt * 32, d0 = dt * 32;
    const int tid = threadIdx.x;
    const int rr = tid >> 5, cc = tid & 31;
#pragma unroll
    for (int p = 0; p < 4; p++) {
        int r = p * 8 + rr;
        s[r][cc] = g_h[((size_t)b * NN + j0 + r) * DD + d0 + cc];
    }
    __syncthreads();
#pragma unroll
    for (int p = 0; p < 4; p++) {
        int d = p * 8 + rr;
        float v = s[cc][d];
        __nv_bfloat16 v1 = __float2bfloat16_rn(v);
        __nv_bfloat16 v2 = __float2bfloat16_rn(v - __bfloat162float(v1));
        size_t o = ((size_t)b * DD + d0 + d) * NN + j0 + cc;
        g_hT1[o] = v1;
        g_hT2[o] = v2;
    }
}

// ---------------------------------------------------------------------------
// K3: scores via warp mma. grid (36 pairs, 16 b), 256 thr.
// e[j,k] = u_j . v_k (K=256, 3 bf16-split products); P = adj>0 ? exp(e) : -1
// ---------------------------------------------------------------------------
#define SC_SMEM (4*MATB)   // 73728; Ts[128][132]f (67584) aliases it

__global__ void __launch_bounds__(256, 1)
scores_mma_kernel(const float* __restrict__ adj) {
    extern __shared__ char smem[];
    const uint32_t sb = smem_u32(smem);
    __nv_bfloat16* mats[4] = { (__nv_bfloat16*)smem,
                               (__nv_bfloat16*)(smem + MATB),
                               (__nv_bfloat16*)(smem + 2*MATB),
                               (__nv_bfloat16*)(smem + 3*MATB) };
    float* Ts = (float*)smem;   // [128][132]

    const int tid = threadIdx.x;
    const int wid = tid >> 5, lane = tid & 31;
    const int b = blockIdx.y;
    int p = blockIdx.x, jT = 0;
    while (p >= 8 - jT) { p -= 8 - jT; jT++; }
    const int kT = jT + p;

    const int mrow = (wid >> 1) * 32, ncol = (wid & 1) * 64;
    float acc[64];
#pragma unroll
    for (int i = 0; i < 64; i++) acc[i] = 0.f;

    const __nv_bfloat16* srcs[4] = { g_u1, g_u2, g_v1, g_v2 };
    const int nb0[4] = { jT * 128, jT * 128, kT * 128, kT * 128 };

#pragma unroll
    for (int chunk = 0; chunk < 4; chunk++) {
        const int k0 = chunk * 64;
        if (chunk) __syncthreads();
        // stage 4 matrices [128 rows][64 bf16] each (padded stride 72)
#pragma unroll
        for (int m = 0; m < 4; m++) {
            const __nv_bfloat16* src = srcs[m];
            char* dst = (char*)mats[m];
#pragma unroll
            for (int it = 0; it < 4; it++) {
                int row = it * 32 + (tid >> 3), f8 = tid & 7;
                uint4 v = *(const uint4*)&src[((size_t)(b * NN + nb0[m] + row)) * 256 + k0 + f8 * 8];
                *(uint4*)(dst + row * (LDO*2) + f8 * 16) = v;
            }
        }
        __syncthreads();
        // 3 products: (u1,v1) (u1,v2) (u2,v1)
#pragma unroll
        for (int pr = 0; pr < 3; pr++) {
            uint32_t Ab = sb + ((pr == 2) ? MATB : 0);
            uint32_t Bb = sb + ((pr == 1) ? 3*MATB : 2*MATB);
#pragma unroll
            for (int ks = 0; ks < 4; ks++) {
                int kk = ks * 16;
                uint32_t af[2][4];
#pragma unroll
                for (int mi = 0; mi < 2; mi++)
                    ldsm4(af[mi], Ab + ((mrow + mi*16 + (lane & 15)) * LDO + kk + (lane >> 4) * 8) * 2);
                uint32_t bf[4][4];
                int lg = lane >> 3, lr = lane & 7;
#pragma unroll
                for (int nb = 0; nb < 4; nb++) {
                    int n = ncol + nb * 16 + (lg >> 1) * 8 + lr;
                    ldsm4(bf[nb], Bb + (n * LDO + kk + (lg & 1) * 8) * 2);
                }
#pragma unroll
                for (int mi = 0; mi < 2; mi++)
#pragma unroll
                    for (int ni = 0; ni < 8; ni++)
                        mma16816(&acc[(mi*8+ni)*4], af[mi], &bf[ni>>1][(ni&1)*2]);
            }
        }
    }

    // accs -> Ts[j-local][k-local]
    __syncthreads();
#pragma unroll
    for (int mi = 0; mi < 2; mi++)
#pragma unroll
        for (int ni = 0; ni < 8; ni++) {
            int row = mrow + mi*16 + (lane >> 2);
            int col = ncol + ni*8 + (lane & 3) * 2;
            float* c = &acc[(mi*8+ni)*4];
            Ts[row * 132 + col]     = c[0];
            Ts[row * 132 + col + 1] = c[1];
            Ts[(row+8) * 132 + col]     = c[2];
            Ts[(row+8) * 132 + col + 1] = c[3];
        }
    __syncthreads();

    const float* adjb = adj + (size_t)b * NN * NN;
    float* Pb = g_P + (size_t)b * NN * NN;

    // direct tile (jT, kT)
#pragma unroll
    for (int it = 0; it < 16; it++) {
        int lin = tid + it * 256;
        int rr = lin >> 5, c4 = lin & 31;
        int jg = jT * 128 + rr, kg = kT * 128 + 4 * c4;
        float4 av = *(const float4*)&adjb[(size_t)jg * NN + kg];
        float4 ev = *(const float4*)&Ts[rr * 132 + 4 * c4];
        float4 pv;
        pv.x = (av.x > 0.f) ? __expf(ev.x) : -1.f;
        pv.y = (av.y > 0.f) ? __expf(ev.y) : -1.f;
        pv.z = (av.z > 0.f) ? __expf(ev.z) : -1.f;
        pv.w = (av.w > 0.f) ? __expf(ev.w) : -1.f;
        *(float4*)&Pb[(size_t)jg * NN + kg] = pv;
    }
    // mirrored tile (kT, jT)
    if (jT != kT) {
#pragma unroll
        for (int it = 0; it < 16; it++) {
            int lin = tid + it * 256;
            int rr = lin >> 5, c4 = lin & 31;
            int kg = kT * 128 + rr, jg = jT * 128 + 4 * c4;
            float4 av = *(const float4*)&adjb[(size_t)kg * NN + jg];
            float e0 = Ts[(4*c4+0) * 132 + rr];
            float e1 = Ts[(4*c4+1) * 132 + rr];
            float e2 = Ts[(4*c4+2) * 132 + rr];
            float e3 = Ts[(4*c4+3) * 132 + rr];
            float4 pv;
            pv.x = (av.x > 0.f) ? __expf(e0) : -1.f;
            pv.y = (av.y > 0.f) ? __expf(e1) : -1.f;
            pv.z = (av.z > 0.f) ? __expf(e2) : -1.f;
            pv.w = (av.w > 0.f) ? __expf(e3) : -1.f;
            *(float4*)&Pb[(size_t)kg * NN + jg] = pv;
        }
    }
}

// ---------------------------------------------------------------------------
// K4: den partials + combine  (rden[k] = 1 / sum_j |P[j,k]|)
// ---------------------------------------------------------------------------
__global__ void den_part_kernel() {
    const int b = blockIdx.y;
    const int cg = blockIdx.x >> 3, seg = blockIdx.x & 7;
    const int col = cg * 256 + threadIdx.x;
    const float* Pb = g_P + (size_t)b * NN * NN + col;
    float s = 0.f;
#pragma unroll 8
    for (int j = seg * 128; j < seg * 128 + 128; j++)
        s += fabsf(Pb[(size_t)j * NN]);
    g_dpart[(b * 8 + seg) * NN + col] = s;
}
__global__ void den_comb_kernel() {
    const int b = blockIdx.y;
    const int col = blockIdx.x * 256 + threadIdx.x;
    float s = 0.f;
#pragma unroll
    for (int seg = 0; seg < 8; seg++)
        s += g_dpart[(b * 8 + seg) * NN + col];
    g_rden[b * NN + col] = 1.0f / s;
}

// ---------------------------------------------------------------------------
// K5: aggregation via warp mma + fused gates. grid (8 iT, 16 b), 256 thr.
// D[i,d] = sum_j attn[i,j] h[j,d]; attn = max(P,0)*rden (bf16 split)
// B operand = hT[b][d][j] (row-major [n][k] == mma .col layout)
// ---------------------------------------------------------------------------
#define AG_SMEM (4*MATB)

__global__ void __launch_bounds__(256, 1)
agg_mma_kernel(const float* __restrict__ x,
               const float* __restrict__ wiu, const float* __restrict__ wix,
               const float* __restrict__ wfu, const float* __restrict__ wfx,
               const float* __restrict__ wou, const float* __restrict__ wox,
               float* __restrict__ out) {
    extern __shared__ char smem[];
    const uint32_t sb = smem_u32(smem);
    char* a1c = smem;
    char* a2c = smem + MATB;
    char* b1c = smem + 2*MATB;
    char* b2c = smem + 3*MATB;
    float* hp = (float*)smem;   // [128][132] epilogue

    const int tid = threadIdx.x;
    const int wid = tid >> 5, lane = tid & 31;
    const int b = blockIdx.y;
    const int i0 = blockIdx.x * 128;

    const int mrow = (wid >> 1) * 32, ncol = (wid & 1) * 64;
    float acc[64];
#pragma unroll
    for (int i = 0; i < 64; i++) acc[i] = 0.f;

    for (int c = 0; c < 16; c++) {
        const int j0 = c * 64;
        if (c) __syncthreads();
        // stage attn splits: a[i-local][j-local]
#pragma unroll
        for (int it = 0; it < 8; it++) {
            int u = tid + it * 256;
            int row = u >> 4, q = u & 15;
            float4 pv = *(const float4*)&g_P[((size_t)(b * NN + i0 + row)) * NN + j0 + 4 * q];
            float4 rd = *(const float4*)&g_rden[b * NN + j0 + 4 * q];
            float av[4];
            av[0] = fmaxf(pv.x, 0.f) * rd.x;
            av[1] = fmaxf(pv.y, 0.f) * rd.y;
            av[2] = fmaxf(pv.z, 0.f) * rd.z;
            av[3] = fmaxf(pv.w, 0.f) * rd.w;
            __nv_bfloat16 v1[4], v2[4];
#pragma unroll
            for (int i = 0; i < 4; i++) {
                v1[i] = __float2bfloat16_rn(av[i]);
                v2[i] = __float2bfloat16_rn(av[i] - __bfloat162float(v1[i]));
            }
            uint32_t off = row * (LDO*2) + q * 8;
            *(uint2*)(a1c + off) = *(uint2*)v1;
            *(uint2*)(a2c + off) = *(uint2*)v2;
        }
        // stage hT splits: b[d][j-local]
#pragma unroll
        for (int it = 0; it < 4; it++) {
            int row = it * 32 + (tid >> 3), f8 = tid & 7;
            size_t so = ((size_t)(b * DD + row)) * NN + j0 + f8 * 8;
            uint4 v1 = *(const uint4*)&g_hT1[so];
            uint4 v2 = *(const uint4*)&g_hT2[so];
            uint32_t off = row * (LDO*2) + f8 * 16;
            *(uint4*)(b1c + off) = v1;
            *(uint4*)(b2c + off) = v2;
        }
        __syncthreads();
        // 3 products: (a1,b1) (a1,b2) (a2,b1)
#pragma unroll
        for (int pr = 0; pr < 3; pr++) {
            uint32_t Ab = sb + ((pr == 2) ? MATB : 0);
            uint32_t Bb = sb + ((pr == 1) ? 3*MATB : 2*MATB);
#pragma unroll
            for (int ks = 0; ks < 4; ks++) {
                int kk = ks * 16;
                uint32_t af[2][4];
#pragma unroll
                for (int mi = 0; mi < 2; mi++)
                    ldsm4(af[mi], Ab + ((mrow + mi*16 + (lane & 15)) * LDO + kk + (lane >> 4) * 8) * 2);
                uint32_t bf[4][4];
                int lg = lane >> 3, lr = lane & 7;
#pragma unroll
                for (int nb = 0; nb < 4; nb++) {
                    int n = ncol + nb * 16 + (lg >> 1) * 8 + lr;
                    ldsm4(bf[nb], Bb + (n * LDO + kk + (lg & 1) * 8) * 2);
                }
#pragma unroll
                for (int mi = 0; mi < 2; mi++)
#pragma unroll
                    for (int ni = 0; ni < 8; ni++)
                        mma16816(&acc[(mi*8+ni)*4], af[mi], &bf[ni>>1][(ni&1)*2]);
            }
        }
    }

    // h' = relu(acc) -> hp[i-local][d]
    __syncthreads();
#pragma unroll
    for (int mi = 0; mi < 2; mi++)
#pragma unroll
        for (int ni = 0; ni < 8; ni++) {
            int row = mrow + mi*16 + (lane >> 2);
            int col = ncol + ni*8 + (lane & 3) * 2;
            float* cc = &acc[(mi*8+ni)*4];
            hp[row * 132 + col]     = fmaxf(cc[0], 0.f);
            hp[row * 132 + col + 1] = fmaxf(cc[1], 0.f);
            hp[(row+8) * 132 + col]     = fmaxf(cc[2], 0.f);
            hp[(row+8) * 132 + col + 1] = fmaxf(cc[3], 0.f);
        }
    __syncthreads();

    float4 ui = *(const float4*)&wiu[lane * 4];
    float4 xi = *(const float4*)&wix[lane * 4];
    float4 uf = *(const float4*)&wfu[lane * 4];
    float4 xf = *(const float4*)&wfx[lane * 4];
    float4 uo = *(const float4*)&wou[lane * 4];
    float4 xo = *(const float4*)&wox[lane * 4];

    for (int r = wid; r < 128; r += 8) {
        size_t n = (size_t)b * NN + i0 + r;
        float4 h4 = *(const float4*)&hp[r * 132 + lane * 4];
        float4 x4 = *(const float4*)&x[n * DD + lane * 4];
        float zi = h4.x*ui.x + h4.y*ui.y + h4.z*ui.z + h4.w*ui.w
                 + x4.x*xi.x + x4.y*xi.y + x4.z*xi.z + x4.w*xi.w;
        float zf = h4.x*uf.x + h4.y*uf.y + h4.z*uf.z + h4.w*uf.w
                 + x4.x*xf.x + x4.y*xf.y + x4.z*xf.z + x4.w*xf.w;
        float zo = h4.x*uo.x + h4.y*uo.y + h4.z*uo.z + h4.w*uo.w
                 + x4.x*xo.x + x4.y*xo.y + x4.z*xo.z + x4.w*xo.w;
#pragma unroll
        for (int off = 16; off; off >>= 1) {
            zi += __shfl_xor_sync(0xffffffffu, zi, off);
            zf += __shfl_xor_sync(0xffffffffu, zf, off);
            zo += __shfl_xor_sync(0xffffffffu, zo, off);
        }
        float ic = 1.f / (1.f + expf(-zi));
        float fc = 1.f / (1.f + expf(-zf));
        float oc = 1.f / (1.f + expf(-zo));
        float4 o;
        o.x = oc * tanhf(ic * h4.x + fc * x4.x);
        o.y = oc * tanhf(ic * h4.y + fc * x4.y);
        o.z = oc * tanhf(ic * h4.z + fc * x4.z);
        o.w = oc * tanhf(ic * h4.w + fc * x4.w);
        *(float4*)&out[n * DD + lane * 4] = o;
    }
}

// ---------------------------------------------------------------------------
extern "C" void kernel_launch(void* const* d_in, const int* in_sizes, int n_in,
                              void* d_out, int out_size) {
    const float* x   = (const float*)d_in[0];
    const float* adj = (const float*)d_in[1];
    const float* Ww  = (const float*)d_in[2];
    const float* Wb  = (const float*)d_in[3];
    const float* A   = (const float*)d_in[4];
    const float* wiu = (const float*)d_in[5];
    const float* wix = (const float*)d_in[6];
    const float* wfu = (const float*)d_in[7];
    const float* wfx = (const float*)d_in[8];
    const float* wou = (const float*)d_in[9];
    const float* wox = (const float*)d_in[10];
    float* out = (float*)d_out;

    float *hptr, *tptr;
    cudaGetSymbolAddress((void**)&hptr, g_h);
    cudaGetSymbolAddress((void**)&tptr, g_t);

    cudaFuncSetAttribute((const void*)gemm128_kernel<true, true>,
                         cudaFuncAttributeMaxDynamicSharedMemorySize, 131072);
    cudaFuncSetAttribute((const void*)gemm128_kernel<false, false>,
                         cudaFuncAttributeMaxDynamicSharedMemorySize, 131072);
    cudaFuncSetAttribute((const void*)scores_mma_kernel,
                         cudaFuncAttributeMaxDynamicSharedMemorySize, SC_SMEM);
    cudaFuncSetAttribute((const void*)agg_mma_kernel,
                         cudaFuncAttributeMaxDynamicSharedMemorySize, AG_SMEM);

    // K1: h = x @ Ww^T + Wb ; K2: t = h @ A
    gemm128_kernel<true, true><<<128, 256, 131072>>>(x, Ww, Wb, hptr);
    gemm128_kernel<false, false><<<128, 256, 131072>>>(hptr, A, nullptr, tptr);
    // prep
    prep_split_kernel<<<2048, 256>>>();
    prep_hT_kernel<<<dim3(128, 16), 256>>>();
    // K3: scores (symmetric pair tiling, warp mma)
    scores_mma_kernel<<<dim3(36, 16), 256, SC_SMEM>>>(adj);
    // K4: denominators
    den_part_kernel<<<dim3(32, 16), 256>>>();
    den_comb_kernel<<<dim3(4, 16), 256>>>();
    // K5: aggregation + fused gates
    agg_mma_kernel<<<dim3(8, 16), 256, AG_SMEM>>>(x, wiu, wix, wfu, wfx, wou, wox, out);
}

// round 9
// speedup vs baseline: 2.1067x; 1.0936x over previous
#include <cuda_runtime.h>
#include <cuda_bf16.h>
#include <cstdint>

#define BB 16
#define NN 1024
#define DD 128
#define BN (BB*NN)

// ---------------- scratch (device globals) ----------------
__device__ float         g_M2[DD*DD];                  // Ww^T @ A
__device__ float         g_b2[DD];                     // Wb @ A
__device__ __nv_bfloat16 g_u1[(size_t)BN*256];         // [t|h] hi
__device__ __nv_bfloat16 g_u2[(size_t)BN*256];         // [t|h] lo
__device__ __nv_bfloat16 g_v1[(size_t)BN*256];         // [h|t] hi
__device__ __nv_bfloat16 g_v2[(size_t)BN*256];         // [h|t] lo
__device__ __nv_bfloat16 g_hT1[(size_t)BB*DD*NN];      // hT[b][d][j] hi
__device__ __nv_bfloat16 g_hT2[(size_t)BB*DD*NN];      // lo
__device__ float         g_P[(size_t)BB*NN*NN];        // 64 MB exp(scores), masked=-1
__device__ float         g_dpart[BB*8*NN];             // column-sum partials per row-tile
__device__ float         g_rden[BB*NN];                // 1/colsum

// ---------------- helpers ----------------
__device__ __forceinline__ uint32_t smem_u32(const void* p) {
    uint32_t a;
    asm("{ .reg .u64 t; cvta.to.shared.u64 t, %1; cvt.u32.u64 %0, t; }" : "=r"(a) : "l"(p));
    return a;
}
__device__ __forceinline__ void ldsm4(uint32_t* r, uint32_t addr) {
    asm volatile("ldmatrix.sync.aligned.m8n8.x4.shared.b16 {%0,%1,%2,%3}, [%4];"
                 : "=r"(r[0]), "=r"(r[1]), "=r"(r[2]), "=r"(r[3]) : "r"(addr));
}
__device__ __forceinline__ void mma16816(float* c, const uint32_t* a, const uint32_t* b) {
    asm volatile("mma.sync.aligned.m16n8k16.row.col.f32.bf16.bf16.f32 "
                 "{%0,%1,%2,%3}, {%4,%5,%6,%7}, {%8,%9}, {%0,%1,%2,%3};"
                 : "+f"(c[0]), "+f"(c[1]), "+f"(c[2]), "+f"(c[3])
                 : "r"(a[0]), "r"(a[1]), "r"(a[2]), "r"(a[3]), "r"(b[0]), "r"(b[1]));
}
#define CP_ASYNC16(dst, src) \
    asm volatile("cp.async.cg.shared.global [%0], [%1], 16;" :: "r"(dst), "l"(src) : "memory")
#define CP_COMMIT() asm volatile("cp.async.commit_group;" ::: "memory")
#define CP_WAIT0()  asm volatile("cp.async.wait_group 0;" ::: "memory")

#define LDO 72            // bf16 elems per smem row (64 data + 8 pad)
#define MATB (128*LDO*2)  // 18432 bytes per staged 128x64 matrix
#define TSTR 129          // float stride for transpose-staging buffers (scalar access only)

__device__ __forceinline__ void split2(float v, __nv_bfloat16& hi, __nv_bfloat16& lo) {
    hi = __float2bfloat16_rn(v);
    lo = __float2bfloat16_rn(v - __bfloat162float(hi));
}

// ---------------------------------------------------------------------------
// prep: M2 = Ww^T @ A  (M2[f][l] = sum_d Ww[d][f]*A[d][l]),  b2 = Wb @ A
// ---------------------------------------------------------------------------
__global__ void prep_M2_kernel(const float* __restrict__ Ww,
                               const float* __restrict__ Wb,
                               const float* __restrict__ A) {
    __shared__ float As[128 * 8];
    const int tid = threadIdx.x;
    const int l0 = blockIdx.x * 8;
#pragma unroll
    for (int q = 0; q < 4; q++) {
        int idx = tid + q * 256;
        int d = idx >> 3, l = idx & 7;
        As[d * 8 + l] = A[d * 128 + l0 + l];
    }
    __syncthreads();
    const int f = tid & 127, g = tid >> 7;
    float s[4] = {0.f, 0.f, 0.f, 0.f};
    for (int d = 0; d < 128; d++) {
        float w = Ww[d * 128 + f];
#pragma unroll
        for (int q = 0; q < 4; q++)
            s[q] += w * As[d * 8 + g * 4 + q];
    }
    *(float4*)&g_M2[f * 128 + l0 + g * 4] = make_float4(s[0], s[1], s[2], s[3]);
    if (tid < 8) {
        float sb2 = 0.f;
        for (int d = 0; d < 128; d++)
            sb2 += Wb[d] * As[d * 8 + tid];
        g_b2[l0 + tid] = sb2;
    }
}

// ---------------------------------------------------------------------------
// fused GEMM: path 0: h = x@Ww^T + Wb  -> u[:,128:256], v[:,0:128], hT splits
//             path 1: t = x@M2   + b2  -> u[:,0:128],   v[:,128:256]
// ---------------------------------------------------------------------------
template<int LDA, int LDB>
__device__ __forceinline__ void mm8x8x4(const float* As, const float* Bs,
                                        int r0, int c0, int l, float acc[8][8]) {
    float a[8][4], bb[4][8];
#pragma unroll
    for (int i = 0; i < 8; i++) {
        float4 v = *(const float4*)&As[(r0 + i) * LDA + l];
        a[i][0]=v.x; a[i][1]=v.y; a[i][2]=v.z; a[i][3]=v.w;
    }
#pragma unroll
    for (int q = 0; q < 4; q++) {
        float4 v0 = *(const float4*)&Bs[(l + q) * LDB + c0];
        float4 v1 = *(const float4*)&Bs[(l + q) * LDB + c0 + 4];
        bb[q][0]=v0.x; bb[q][1]=v0.y; bb[q][2]=v0.z; bb[q][3]=v0.w;
        bb[q][4]=v1.x; bb[q][5]=v1.y; bb[q][6]=v1.z; bb[q][7]=v1.w;
    }
#pragma unroll
    for (int q = 0; q < 4; q++)
#pragma unroll
        for (int i = 0; i < 8; i++)
#pragma unroll
            for (int j = 0; j < 8; j++)
                acc[i][j] += a[i][q] * bb[q][j];
}

__global__ void __launch_bounds__(256, 1)
gemmht_kernel(const float* __restrict__ x, const float* __restrict__ Ww,
              const float* __restrict__ Wb) {
    extern __shared__ float smemf[];
    float* As = smemf;
    float* Bs = smemf + 128 * 128;
    const int tid = threadIdx.x;
    const int m0 = blockIdx.x * 128;
    const int path = blockIdx.y;        // 0 = h, 1 = t

    const float4* Ag = (const float4*)(x + (size_t)m0 * 128);
#pragma unroll
    for (int it = 0; it < 16; it++)
        ((float4*)As)[tid + it * 256] = Ag[tid + it * 256];
    if (path == 0) {
#pragma unroll
        for (int it = 0; it < 16; it++) {
            int lin = tid + it * 256;
            int c = lin & 127, k4 = lin >> 7;
            float4 v = ((const float4*)Ww)[c * 32 + k4];
            Bs[(4*k4+0)*128+c]=v.x; Bs[(4*k4+1)*128+c]=v.y;
            Bs[(4*k4+2)*128+c]=v.z; Bs[(4*k4+3)*128+c]=v.w;
        }
    } else {
#pragma unroll
        for (int it = 0; it < 16; it++)
            ((float4*)Bs)[tid + it * 256] = ((const float4*)g_M2)[tid + it * 256];
    }
    __syncthreads();
    const int r0 = (tid >> 4) * 8, c0 = (tid & 15) * 8;
    float acc[8][8] = {};
#pragma unroll
    for (int l = 0; l < 128; l += 4)
        mm8x8x4<128, 128>(As, Bs, r0, c0, l, acc);

    const float* bias = path ? g_b2 : Wb;
    float bv[8];
#pragma unroll
    for (int j = 0; j < 8; j++) bv[j] = bias[c0 + j];
#pragma unroll
    for (int i = 0; i < 8; i++)
#pragma unroll
        for (int j = 0; j < 8; j++)
            acc[i][j] += bv[j];

    // write u/v bf16 splits (u=[t|h], v=[h|t])
#pragma unroll
    for (int i = 0; i < 8; i++) {
        int node = m0 + r0 + i;
        __nv_bfloat16 hi[8], lo[8];
#pragma unroll
        for (int j = 0; j < 8; j++) split2(acc[i][j], hi[j], lo[j]);
        size_t bu = (size_t)node * 256 + c0 + (path ? 0 : 128);
        size_t bvv = (size_t)node * 256 + c0 + (path ? 128 : 0);
        *(uint4*)&g_u1[bu]  = *(uint4*)hi;
        *(uint4*)&g_u2[bu]  = *(uint4*)lo;
        *(uint4*)&g_v1[bvv] = *(uint4*)hi;
        *(uint4*)&g_v2[bvv] = *(uint4*)lo;
    }

    if (path == 0) {
        // hT[b][d][j] splits via smem transpose (scalar smem access, stride 129)
        __syncthreads();
        float* Ts = smemf;   // [128][TSTR]
#pragma unroll
        for (int i = 0; i < 8; i++)
#pragma unroll
            for (int j = 0; j < 8; j++)
                Ts[(r0 + i) * TSTR + c0 + j] = acc[i][j];
        __syncthreads();
        const int bb_ = m0 >> 10, j0 = m0 & 1023;
#pragma unroll
        for (int it = 0; it < 32; it++) {
            int idx = it * 256 + tid;
            int d = idx >> 6, jp = idx & 63;
            float v0 = Ts[(2 * jp) * TSTR + d];
            float v1 = Ts[(2 * jp + 1) * TSTR + d];
            __nv_bfloat16 h0, l0_, h1, l1;
            split2(v0, h0, l0_);
            split2(v1, h1, l1);
            size_t o = ((size_t)bb_ * DD + d) * NN + j0 + 2 * jp;
            *(uint32_t*)&g_hT1[o] = (uint32_t)__bfloat16_as_ushort(h0) |
                                    ((uint32_t)__bfloat16_as_ushort(h1) << 16);
            *(uint32_t*)&g_hT2[o] = (uint32_t)__bfloat16_as_ushort(l0_) |
                                    ((uint32_t)__bfloat16_as_ushort(l1) << 16);
        }
    }
}

// ---------------------------------------------------------------------------
// warp-mma core: 3 products x 4 k-slices on 4 staged 128x64 matrices
// ---------------------------------------------------------------------------
__device__ __forceinline__ void mma_block(uint32_t base, int mrow, int ncol,
                                          int lane, float* acc) {
#pragma unroll
    for (int pr = 0; pr < 3; pr++) {
        uint32_t Ab = base + ((pr == 2) ? MATB : 0);
        uint32_t Bb = base + ((pr == 1) ? 3 * MATB : 2 * MATB);
#pragma unroll
        for (int ks = 0; ks < 4; ks++) {
            int kk = ks * 16;
            uint32_t af[2][4];
#pragma unroll
            for (int mi = 0; mi < 2; mi++)
                ldsm4(af[mi], Ab + ((mrow + mi*16 + (lane & 15)) * LDO + kk + (lane >> 4) * 8) * 2);
            uint32_t bf[4][4];
            int lg = lane >> 3, lr = lane & 7;
#pragma unroll
            for (int nb = 0; nb < 4; nb++) {
                int n = ncol + nb * 16 + (lg >> 1) * 8 + lr;
                ldsm4(bf[nb], Bb + (n * LDO + kk + (lg & 1) * 8) * 2);
            }
#pragma unroll
            for (int mi = 0; mi < 2; mi++)
#pragma unroll
                for (int ni = 0; ni < 8; ni++)
                    mma16816(&acc[(mi*8+ni)*4], af[mi], &bf[ni>>1][(ni&1)*2]);
        }
    }
}

// ---------------------------------------------------------------------------
// K3: scores. grid (36 pairs, 16 b), 256 thr, 2 CTA/SM.
// e[j,k] = u_j.v_k ; P = adj>0 ? exp(e) : -1 ; fused column-sum partials
// ---------------------------------------------------------------------------
#define SC_SMEM (4*MATB)   // 73728; epilogue: Ts[128][129] (66048) + red (4096)

__global__ void __launch_bounds__(256, 2)
scores_mma_kernel(const float* __restrict__ adj) {
    extern __shared__ char smem[];
    const uint32_t sb = smem_u32(smem);
    float* Ts = (float*)smem;                    // [128][TSTR], scalar access only
    float* red = (float*)(smem + 66048);         // [8][128]

    const int tid = threadIdx.x;
    const int wid = tid >> 5, lane = tid & 31;
    const int b = blockIdx.y;
    int p = blockIdx.x, jT = 0;
    while (p >= 8 - jT) { p -= 8 - jT; jT++; }
    const int kT = jT + p;

    const int mrow = (wid >> 1) * 32, ncol = (wid & 1) * 64;
    float acc[64];
#pragma unroll
    for (int i = 0; i < 64; i++) acc[i] = 0.f;

    const __nv_bfloat16* srcs[4] = { g_u1, g_u2, g_v1, g_v2 };
    const int nb0[4] = { jT * 128, jT * 128, kT * 128, kT * 128 };

#pragma unroll
    for (int chunk = 0; chunk < 4; chunk++) {
        const int k0 = chunk * 64;
        if (chunk) __syncthreads();
#pragma unroll
        for (int m = 0; m < 4; m++) {
            const __nv_bfloat16* src = srcs[m];
            uint32_t smb = sb + m * MATB;
#pragma unroll
            for (int it = 0; it < 4; it++) {
                int row = it * 32 + (tid >> 3), f8 = tid & 7;
                const void* g = &src[((size_t)(b * NN + nb0[m] + row)) * 256 + k0 + f8 * 8];
                CP_ASYNC16(smb + row * (LDO*2) + f8 * 16, g);
            }
        }
        CP_COMMIT();
        CP_WAIT0();
        __syncthreads();
        mma_block(sb, mrow, ncol, lane, acc);
    }

    // acc -> Ts (scalar stores)
    __syncthreads();
#pragma unroll
    for (int mi = 0; mi < 2; mi++)
#pragma unroll
        for (int ni = 0; ni < 8; ni++) {
            int row = mrow + mi*16 + (lane >> 2);
            int col = ncol + ni*8 + (lane & 3) * 2;
            float* c = &acc[(mi*8+ni)*4];
            Ts[row * TSTR + col]           = c[0];
            Ts[row * TSTR + col + 1]       = c[1];
            Ts[(row + 8) * TSTR + col]     = c[2];
            Ts[(row + 8) * TSTR + col + 1] = c[3];
        }
    __syncthreads();

    const float* adjb = adj + (size_t)b * NN * NN;
    float* Pb = g_P + (size_t)b * NN * NN;
    const int a = tid >> 5, c4 = tid & 31;

    // direct tile (jT rows, kT cols) + column partial sums
    float cs[4] = {0.f, 0.f, 0.f, 0.f};
#pragma unroll
    for (int it = 0; it < 16; it++) {
        int rr = a + 8 * it;
        int jg = jT * 128 + rr, kg = kT * 128 + 4 * c4;
        float4 av = *(const float4*)&adjb[(size_t)jg * NN + kg];
        const float* tr = &Ts[rr * TSTR + 4 * c4];
        float4 pv;
        pv.x = (av.x > 0.f) ? __expf(tr[0]) : -1.f;
        pv.y = (av.y > 0.f) ? __expf(tr[1]) : -1.f;
        pv.z = (av.z > 0.f) ? __expf(tr[2]) : -1.f;
        pv.w = (av.w > 0.f) ? __expf(tr[3]) : -1.f;
        *(float4*)&Pb[(size_t)jg * NN + kg] = pv;
        cs[0] += fabsf(pv.x); cs[1] += fabsf(pv.y);
        cs[2] += fabsf(pv.z); cs[3] += fabsf(pv.w);
    }
    *(float4*)&red[a * 128 + 4 * c4] = make_float4(cs[0], cs[1], cs[2], cs[3]);
    __syncthreads();
    if (tid < 128) {
        float s = 0.f;
#pragma unroll
        for (int q = 0; q < 8; q++) s += red[q * 128 + tid];
        g_dpart[(b * 8 + jT) * NN + kT * 128 + tid] = s;
    }
    __syncthreads();

    // mirrored tile (kT rows, jT cols)
    if (jT != kT) {
        float cs2[4] = {0.f, 0.f, 0.f, 0.f};
#pragma unroll
        for (int it = 0; it < 16; it++) {
            int rr = a + 8 * it;
            int kg = kT * 128 + rr, jg = jT * 128 + 4 * c4;
            float4 av = *(const float4*)&adjb[(size_t)kg * NN + jg];
            float e0 = Ts[(4*c4+0) * TSTR + rr];
            float e1 = Ts[(4*c4+1) * TSTR + rr];
            float e2 = Ts[(4*c4+2) * TSTR + rr];
            float e3 = Ts[(4*c4+3) * TSTR + rr];
            float4 pv;
            pv.x = (av.x > 0.f) ? __expf(e0) : -1.f;
            pv.y = (av.y > 0.f) ? __expf(e1) : -1.f;
            pv.z = (av.z > 0.f) ? __expf(e2) : -1.f;
            pv.w = (av.w > 0.f) ? __expf(e3) : -1.f;
            *(float4*)&Pb[(size_t)kg * NN + jg] = pv;
            cs2[0] += fabsf(pv.x); cs2[1] += fabsf(pv.y);
            cs2[2] += fabsf(pv.z); cs2[3] += fabsf(pv.w);
        }
        __syncthreads();
        *(float4*)&red[a * 128 + 4 * c4] = make_float4(cs2[0], cs2[1], cs2[2], cs2[3]);
        __syncthreads();
        if (tid < 128) {
            float s = 0.f;
#pragma unroll
            for (int q = 0; q < 8; q++) s += red[q * 128 + tid];
            g_dpart[(b * 8 + kT) * NN + jT * 128 + tid] = s;
        }
    }
}

// ---------------------------------------------------------------------------
// K4: combine 8 partials -> rden
// ---------------------------------------------------------------------------
__global__ void den_comb_kernel() {
    const int b = blockIdx.y;
    const int col = blockIdx.x * 512 + threadIdx.x;
    float s = 0.f;
#pragma unroll
    for (int seg = 0; seg < 8; seg++)
        s += g_dpart[(b * 8 + seg) * NN + col];
    g_rden[b * NN + col] = 1.0f / s;
}

// ---------------------------------------------------------------------------
// K5: aggregation, software-pipelined, + fused gates. grid (8 iT, 16 b).
// ---------------------------------------------------------------------------
#define AG_SMEM (8*MATB)   // double buffer: 147456

__global__ void __launch_bounds__(256, 1)
agg_mma_kernel(const float* __restrict__ x,
               const float* __restrict__ wiu, const float* __restrict__ wix,
               const float* __restrict__ wfu, const float* __restrict__ wfx,
               const float* __restrict__ wou, const float* __restrict__ wox,
               float* __restrict__ out) {
    extern __shared__ char smem[];
    const uint32_t sb = smem_u32(smem);
    const int tid = threadIdx.x;
    const int wid = tid >> 5, lane = tid & 31;
    const int b = blockIdx.y;
    const int i0 = blockIdx.x * 128;
    const int mrow = (wid >> 1) * 32, ncol = (wid & 1) * 64;

    float acc[64];
#pragma unroll
    for (int i = 0; i < 64; i++) acc[i] = 0.f;

    float4 preg[8];

    auto stage_hT = [&](int bufi, int c) {
        const int j0 = c * 64;
        uint32_t b1 = sb + bufi * (4*MATB) + 2*MATB;
        uint32_t b2 = b1 + MATB;
#pragma unroll
        for (int it = 0; it < 4; it++) {
            int row = it * 32 + (tid >> 3), f8 = tid & 7;
            size_t so = ((size_t)(b * DD + row)) * NN + j0 + f8 * 8;
            CP_ASYNC16(b1 + row * (LDO*2) + f8 * 16, (const void*)&g_hT1[so]);
            CP_ASYNC16(b2 + row * (LDO*2) + f8 * 16, (const void*)&g_hT2[so]);
        }
        CP_COMMIT();
    };
    auto load_P = [&](int c) {
        const int j0 = c * 64;
#pragma unroll
        for (int it = 0; it < 8; it++) {
            int u = tid + it * 256;
            int row = u >> 4, q = u & 15;
            preg[it] = *(const float4*)&g_P[((size_t)(b * NN + i0 + row)) * NN + j0 + 4 * q];
        }
    };
    auto store_attn = [&](int bufi, int c) {
        const int j0 = c * 64;
        char* a1c = smem + bufi * (4*MATB);
        char* a2c = a1c + MATB;
#pragma unroll
        for (int it = 0; it < 8; it++) {
            int u = tid + it * 256;
            int row = u >> 4, q = u & 15;
            float4 rd = *(const float4*)&g_rden[b * NN + j0 + 4 * q];
            float av[4];
            av[0] = fmaxf(preg[it].x, 0.f) * rd.x;
            av[1] = fmaxf(preg[it].y, 0.f) * rd.y;
            av[2] = fmaxf(preg[it].z, 0.f) * rd.z;
            av[3] = fmaxf(preg[it].w, 0.f) * rd.w;
            __nv_bfloat16 v1[4], v2[4];
#pragma unroll
            for (int i = 0; i < 4; i++) split2(av[i], v1[i], v2[i]);
            uint32_t off = row * (LDO*2) + q * 8;
            *(uint2*)(a1c + off) = *(uint2*)v1;
            *(uint2*)(a2c + off) = *(uint2*)v2;
        }
    };

    // prologue: stage chunk 0
    stage_hT(0, 0);
    load_P(0);
    store_attn(0, 0);
    CP_WAIT0();
    __syncthreads();

    for (int c = 0; c < 16; c++) {
        const int cur = c & 1, nxt = cur ^ 1;
        if (c < 15) {
            stage_hT(nxt, c + 1);
            load_P(c + 1);
        }
        mma_block(sb + cur * (4*MATB), mrow, ncol, lane, acc);
        if (c < 15) store_attn(nxt, c + 1);
        CP_WAIT0();
        __syncthreads();
    }

    // h' = relu(acc) -> hp [128][132] (132 floats = 528B, 16B-aligned rows)
    float* hp = (float*)smem;
#pragma unroll
    for (int mi = 0; mi < 2; mi++)
#pragma unroll
        for (int ni = 0; ni < 8; ni++) {
            int row = mrow + mi*16 + (lane >> 2);
            int col = ncol + ni*8 + (lane & 3) * 2;
            float* cc = &acc[(mi*8+ni)*4];
            hp[row * 132 + col]         = fmaxf(cc[0], 0.f);
            hp[row * 132 + col + 1]     = fmaxf(cc[1], 0.f);
            hp[(row+8) * 132 + col]     = fmaxf(cc[2], 0.f);
            hp[(row+8) * 132 + col + 1] = fmaxf(cc[3], 0.f);
        }
    __syncthreads();

    float4 ui = *(const float4*)&wiu[lane * 4];
    float4 xi = *(const float4*)&wix[lane * 4];
    float4 uf = *(const float4*)&wfu[lane * 4];
    float4 xf = *(const float4*)&wfx[lane * 4];
    float4 uo = *(const float4*)&wou[lane * 4];
    float4 xo = *(const float4*)&wox[lane * 4];

    for (int r = wid; r < 128; r += 8) {
        size_t n = (size_t)b * NN + i0 + r;
        float4 h4 = *(const float4*)&hp[r * 132 + lane * 4];
        float4 x4 = *(const float4*)&x[n * DD + lane * 4];
        float zi = h4.x*ui.x + h4.y*ui.y + h4.z*ui.z + h4.w*ui.w
                 + x4.x*xi.x + x4.y*xi.y + x4.z*xi.z + x4.w*xi.w;
        float zf = h4.x*uf.x + h4.y*uf.y + h4.z*uf.z + h4.w*uf.w
                 + x4.x*xf.x + x4.y*xf.y + x4.z*xf.z + x4.w*xf.w;
        float zo = h4.x*uo.x + h4.y*uo.y + h4.z*uo.z + h4.w*uo.w
                 + x4.x*xo.x + x4.y*xo.y + x4.z*xo.z + x4.w*xo.w;
#pragma unroll
        for (int off = 16; off; off >>= 1) {
            zi += __shfl_xor_sync(0xffffffffu, zi, off);
            zf += __shfl_xor_sync(0xffffffffu, zf, off);
            zo += __shfl_xor_sync(0xffffffffu, zo, off);
        }
        float ic = 1.f / (1.f + expf(-zi));
        float fc = 1.f / (1.f + expf(-zf));
        float oc = 1.f / (1.f + expf(-zo));
        float4 o;
        o.x = oc * tanhf(ic * h4.x + fc * x4.x);
        o.y = oc * tanhf(ic * h4.y + fc * x4.y);
        o.z = oc * tanhf(ic * h4.z + fc * x4.z);
        o.w = oc * tanhf(ic * h4.w + fc * x4.w);
        *(float4*)&out[n * DD + lane * 4] = o;
    }
}

// ---------------------------------------------------------------------------
extern "C" void kernel_launch(void* const* d_in, const int* in_sizes, int n_in,
                              void* d_out, int out_size) {
    const float* x   = (const float*)d_in[0];
    const float* adj = (const float*)d_in[1];
    const float* Ww  = (const float*)d_in[2];
    const float* Wb  = (const float*)d_in[3];
    const float* A   = (const float*)d_in[4];
    const float* wiu = (const float*)d_in[5];
    const float* wix = (const float*)d_in[6];
    const float* wfu = (const float*)d_in[7];
    const float* wfx = (const float*)d_in[8];
    const float* wou = (const float*)d_in[9];
    const float* wox = (const float*)d_in[10];
    float* out = (float*)d_out;

    cudaFuncSetAttribute((const void*)gemmht_kernel,
                         cudaFuncAttributeMaxDynamicSharedMemorySize, 131072);
    cudaFuncSetAttribute((const void*)scores_mma_kernel,
                         cudaFuncAttributeMaxDynamicSharedMemorySize, SC_SMEM);
    cudaFuncSetAttribute((const void*)agg_mma_kernel,
                         cudaFuncAttributeMaxDynamicSharedMemorySize, AG_SMEM);

    prep_M2_kernel<<<16, 256>>>(Ww, Wb, A);
    gemmht_kernel<<<dim3(128, 2), 256, 131072>>>(x, Ww, Wb);
    scores_mma_kernel<<<dim3(36, 16), 256, SC_SMEM>>>(adj);
    den_comb_kernel<<<dim3(2, 16), 512>>>();
    agg_mma_kernel<<<dim3(8, 16), 256, AG_SMEM>>>(x, wiu, wix, wfu, wfx, wou, wox, out);
}

// round 10
// speedup vs baseline: 2.4293x; 1.1532x over previous
#include <cuda_runtime.h>
#include <cuda_bf16.h>
#include <cstdint>

#define BB 16
#define NN 1024
#define DD 128
#define BN (BB*NN)

// ---------------- scratch (device globals) ----------------
__device__ float         g_M2[DD*DD];                  // Ww^T @ A
__device__ float         g_b2[DD];                     // Wb @ A
__device__ __nv_bfloat16 g_u1[(size_t)BN*256];         // [t|h] hi
__device__ __nv_bfloat16 g_u2[(size_t)BN*256];         // [t|h] lo
__device__ __nv_bfloat16 g_v1[(size_t)BN*256];         // [h|t] hi
__device__ __nv_bfloat16 g_v2[(size_t)BN*256];         // [h|t] lo
__device__ __nv_bfloat16 g_hT1[(size_t)BB*DD*NN];      // hT[b][d][j] hi
__device__ __nv_bfloat16 g_hT2[(size_t)BB*DD*NN];      // lo
__device__ float         g_P[(size_t)BB*NN*NN];        // 64 MB exp(scores), masked=-1
__device__ float         g_dpart[BB*8*NN];             // column-sum partials per row-tile
__device__ float         g_rden[BB*NN];                // 1/colsum

// ---------------- helpers ----------------
__device__ __forceinline__ uint32_t smem_u32(const void* p) {
    uint32_t a;
    asm("{ .reg .u64 t; cvta.to.shared.u64 t, %1; cvt.u32.u64 %0, t; }" : "=r"(a) : "l"(p));
    return a;
}
__device__ __forceinline__ void ldsm4(uint32_t* r, uint32_t addr) {
    asm volatile("ldmatrix.sync.aligned.m8n8.x4.shared.b16 {%0,%1,%2,%3}, [%4];"
                 : "=r"(r[0]), "=r"(r[1]), "=r"(r[2]), "=r"(r[3]) : "r"(addr));
}
__device__ __forceinline__ void mma16816(float* c, const uint32_t* a, const uint32_t* b) {
    asm volatile("mma.sync.aligned.m16n8k16.row.col.f32.bf16.bf16.f32 "
                 "{%0,%1,%2,%3}, {%4,%5,%6,%7}, {%8,%9}, {%0,%1,%2,%3};"
                 : "+f"(c[0]), "+f"(c[1]), "+f"(c[2]), "+f"(c[3])
                 : "r"(a[0]), "r"(a[1]), "r"(a[2]), "r"(a[3]), "r"(b[0]), "r"(b[1]));
}
#define CP_ASYNC16(dst, src) \
    asm volatile("cp.async.cg.shared.global [%0], [%1], 16;" :: "r"(dst), "l"(src) : "memory")
#define CP_COMMIT() asm volatile("cp.async.commit_group;" ::: "memory")
#define CP_WAIT0()  asm volatile("cp.async.wait_group 0;" ::: "memory")

#define LDO 72            // bf16 elems per smem row (64 data + 8 pad)
#define MATB (128*LDO*2)  // 18432 bytes per staged 128x64 matrix
#define MATB64 (64*LDO*2) // 9216 bytes per staged 64x64 matrix
#define TSTR 129          // float stride for transpose-staging (scalar access only)

__device__ __forceinline__ void split2(float v, __nv_bfloat16& hi, __nv_bfloat16& lo) {
    hi = __float2bfloat16_rn(v);
    lo = __float2bfloat16_rn(v - __bfloat162float(hi));
}

// ---------------------------------------------------------------------------
// prep: M2 = Ww^T @ A,  b2 = Wb @ A
// ---------------------------------------------------------------------------
__global__ void prep_M2_kernel(const float* __restrict__ Ww,
                               const float* __restrict__ Wb,
                               const float* __restrict__ A) {
    __shared__ float As[128 * 8];
    const int tid = threadIdx.x;
    const int l0 = blockIdx.x * 8;
#pragma unroll
    for (int q = 0; q < 4; q++) {
        int idx = tid + q * 256;
        int d = idx >> 3, l = idx & 7;
        As[d * 8 + l] = A[d * 128 + l0 + l];
    }
    __syncthreads();
    const int f = tid & 127, g = tid >> 7;
    float s[4] = {0.f, 0.f, 0.f, 0.f};
    for (int d = 0; d < 128; d++) {
        float w = Ww[d * 128 + f];
#pragma unroll
        for (int q = 0; q < 4; q++)
            s[q] += w * As[d * 8 + g * 4 + q];
    }
    *(float4*)&g_M2[f * 128 + l0 + g * 4] = make_float4(s[0], s[1], s[2], s[3]);
    if (tid < 8) {
        float sb2 = 0.f;
        for (int d = 0; d < 128; d++)
            sb2 += Wb[d] * As[d * 8 + tid];
        g_b2[l0 + tid] = sb2;
    }
}

// ---------------------------------------------------------------------------
// fused GEMM: path 0: h = x@Ww^T + Wb -> u[:,128:256], v[:,0:128], hT splits
//             path 1: t = x@M2   + b2 -> u[:,0:128],   v[:,128:256]
// ---------------------------------------------------------------------------
template<int LDA, int LDB>
__device__ __forceinline__ void mm8x8x4(const float* As, const float* Bs,
                                        int r0, int c0, int l, float acc[8][8]) {
    float a[8][4], bb[4][8];
#pragma unroll
    for (int i = 0; i < 8; i++) {
        float4 v = *(const float4*)&As[(r0 + i) * LDA + l];
        a[i][0]=v.x; a[i][1]=v.y; a[i][2]=v.z; a[i][3]=v.w;
    }
#pragma unroll
    for (int q = 0; q < 4; q++) {
        float4 v0 = *(const float4*)&Bs[(l + q) * LDB + c0];
        float4 v1 = *(const float4*)&Bs[(l + q) * LDB + c0 + 4];
        bb[q][0]=v0.x; bb[q][1]=v0.y; bb[q][2]=v0.z; bb[q][3]=v0.w;
        bb[q][4]=v1.x; bb[q][5]=v1.y; bb[q][6]=v1.z; bb[q][7]=v1.w;
    }
#pragma unroll
    for (int q = 0; q < 4; q++)
#pragma unroll
        for (int i = 0; i < 8; i++)
#pragma unroll
            for (int j = 0; j < 8; j++)
                acc[i][j] += a[i][q] * bb[q][j];
}

__global__ void __launch_bounds__(256, 1)
gemmht_kernel(const float* __restrict__ x, const float* __restrict__ Ww,
              const float* __restrict__ Wb) {
    extern __shared__ float smemf[];
    float* As = smemf;
    float* Bs = smemf + 128 * 128;
    const int tid = threadIdx.x;
    const int m0 = blockIdx.x * 128;
    const int path = blockIdx.y;

    const float4* Ag = (const float4*)(x + (size_t)m0 * 128);
#pragma unroll
    for (int it = 0; it < 16; it++)
        ((float4*)As)[tid + it * 256] = Ag[tid + it * 256];
    if (path == 0) {
#pragma unroll
        for (int it = 0; it < 16; it++) {
            int lin = tid + it * 256;
            int c = lin & 127, k4 = lin >> 7;
            float4 v = ((const float4*)Ww)[c * 32 + k4];
            Bs[(4*k4+0)*128+c]=v.x; Bs[(4*k4+1)*128+c]=v.y;
            Bs[(4*k4+2)*128+c]=v.z; Bs[(4*k4+3)*128+c]=v.w;
        }
    } else {
#pragma unroll
        for (int it = 0; it < 16; it++)
            ((float4*)Bs)[tid + it * 256] = ((const float4*)g_M2)[tid + it * 256];
    }
    __syncthreads();
    const int r0 = (tid >> 4) * 8, c0 = (tid & 15) * 8;
    float acc[8][8] = {};
#pragma unroll
    for (int l = 0; l < 128; l += 4)
        mm8x8x4<128, 128>(As, Bs, r0, c0, l, acc);

    const float* bias = path ? g_b2 : Wb;
    float bv[8];
#pragma unroll
    for (int j = 0; j < 8; j++) bv[j] = bias[c0 + j];
#pragma unroll
    for (int i = 0; i < 8; i++)
#pragma unroll
        for (int j = 0; j < 8; j++)
            acc[i][j] += bv[j];

#pragma unroll
    for (int i = 0; i < 8; i++) {
        int node = m0 + r0 + i;
        __nv_bfloat16 hi[8], lo[8];
#pragma unroll
        for (int j = 0; j < 8; j++) split2(acc[i][j], hi[j], lo[j]);
        size_t bu = (size_t)node * 256 + c0 + (path ? 0 : 128);
        size_t bvv = (size_t)node * 256 + c0 + (path ? 128 : 0);
        *(uint4*)&g_u1[bu]  = *(uint4*)hi;
        *(uint4*)&g_u2[bu]  = *(uint4*)lo;
        *(uint4*)&g_v1[bvv] = *(uint4*)hi;
        *(uint4*)&g_v2[bvv] = *(uint4*)lo;
    }

    if (path == 0) {
        __syncthreads();
        float* Ts = smemf;   // [128][TSTR], scalar access
#pragma unroll
        for (int i = 0; i < 8; i++)
#pragma unroll
            for (int j = 0; j < 8; j++)
                Ts[(r0 + i) * TSTR + c0 + j] = acc[i][j];
        __syncthreads();
        const int bb_ = m0 >> 10, j0 = m0 & 1023;
#pragma unroll
        for (int it = 0; it < 32; it++) {
            int idx = it * 256 + tid;
            int d = idx >> 6, jp = idx & 63;
            float v0 = Ts[(2 * jp) * TSTR + d];
            float v1 = Ts[(2 * jp + 1) * TSTR + d];
            __nv_bfloat16 h0, l0_, h1, l1;
            split2(v0, h0, l0_);
            split2(v1, h1, l1);
            size_t o = ((size_t)bb_ * DD + d) * NN + j0 + 2 * jp;
            *(uint32_t*)&g_hT1[o] = (uint32_t)__bfloat16_as_ushort(h0) |
                                    ((uint32_t)__bfloat16_as_ushort(h1) << 16);
            *(uint32_t*)&g_hT2[o] = (uint32_t)__bfloat16_as_ushort(l0_) |
                                    ((uint32_t)__bfloat16_as_ushort(l1) << 16);
        }
    }
}

// ---------------------------------------------------------------------------
// warp-mma core, fragment-reuse version (M=128 tiles): per k-slice load
// a1,a2,b1 once -> (a1*b1, a2*b1); load b2 -> (a1*b2). 12 ldsm4 / k-slice.
// ---------------------------------------------------------------------------
__device__ __forceinline__ void mma_block(uint32_t base, int mrow, int ncol,
                                          int lane, float* acc) {
    const uint32_t A1 = base, A2 = base + MATB;
    const uint32_t B1 = base + 2 * MATB, B2 = base + 3 * MATB;
    const int lg = lane >> 3, lr = lane & 7;
#pragma unroll
    for (int ks = 0; ks < 4; ks++) {
        const int kk = ks * 16;
        uint32_t a1f[2][4], a2f[2][4];
#pragma unroll
        for (int mi = 0; mi < 2; mi++) {
            uint32_t ro = ((mrow + mi*16 + (lane & 15)) * LDO + kk + (lane >> 4) * 8) * 2;
            ldsm4(a1f[mi], A1 + ro);
            ldsm4(a2f[mi], A2 + ro);
        }
        uint32_t bf[4][4];
#pragma unroll
        for (int nb = 0; nb < 4; nb++) {
            int n = ncol + nb * 16 + (lg >> 1) * 8 + lr;
            ldsm4(bf[nb], B1 + (n * LDO + kk + (lg & 1) * 8) * 2);
        }
#pragma unroll
        for (int mi = 0; mi < 2; mi++)
#pragma unroll
            for (int ni = 0; ni < 8; ni++) {
                mma16816(&acc[(mi*8+ni)*4], a1f[mi], &bf[ni>>1][(ni&1)*2]);
                mma16816(&acc[(mi*8+ni)*4], a2f[mi], &bf[ni>>1][(ni&1)*2]);
            }
#pragma unroll
        for (int nb = 0; nb < 4; nb++) {
            int n = ncol + nb * 16 + (lg >> 1) * 8 + lr;
            ldsm4(bf[nb], B2 + (n * LDO + kk + (lg & 1) * 8) * 2);
        }
#pragma unroll
        for (int mi = 0; mi < 2; mi++)
#pragma unroll
            for (int ni = 0; ni < 8; ni++)
                mma16816(&acc[(mi*8+ni)*4], a1f[mi], &bf[ni>>1][(ni&1)*2]);
    }
}

// ---------------------------------------------------------------------------
// K3: scores. grid (36 pairs, 16 b), 256 thr, 2 CTA/SM.
// ---------------------------------------------------------------------------
#define SC_SMEM (4*MATB)   // 73728; epilogue: Ts[128][129] (66048) + red (4096)

__global__ void __launch_bounds__(256, 2)
scores_mma_kernel(const float* __restrict__ adj) {
    extern __shared__ char smem[];
    const uint32_t sb = smem_u32(smem);
    float* Ts = (float*)smem;
    float* red = (float*)(smem + 66048);

    const int tid = threadIdx.x;
    const int wid = tid >> 5, lane = tid & 31;
    const int b = blockIdx.y;
    int p = blockIdx.x, jT = 0;
    while (p >= 8 - jT) { p -= 8 - jT; jT++; }
    const int kT = jT + p;

    const int mrow = (wid >> 1) * 32, ncol = (wid & 1) * 64;
    float acc[64];
#pragma unroll
    for (int i = 0; i < 64; i++) acc[i] = 0.f;

    const __nv_bfloat16* srcs[4] = { g_u1, g_u2, g_v1, g_v2 };
    const int nb0[4] = { jT * 128, jT * 128, kT * 128, kT * 128 };

#pragma unroll
    for (int chunk = 0; chunk < 4; chunk++) {
        const int k0 = chunk * 64;
        if (chunk) __syncthreads();
#pragma unroll
        for (int m = 0; m < 4; m++) {
            const __nv_bfloat16* src = srcs[m];
            uint32_t smb = sb + m * MATB;
#pragma unroll
            for (int it = 0; it < 4; it++) {
                int row = it * 32 + (tid >> 3), f8 = tid & 7;
                const void* g = &src[((size_t)(b * NN + nb0[m] + row)) * 256 + k0 + f8 * 8];
                CP_ASYNC16(smb + row * (LDO*2) + f8 * 16, g);
            }
        }
        CP_COMMIT();
        CP_WAIT0();
        __syncthreads();
        mma_block(sb, mrow, ncol, lane, acc);
    }

    __syncthreads();
#pragma unroll
    for (int mi = 0; mi < 2; mi++)
#pragma unroll
        for (int ni = 0; ni < 8; ni++) {
            int row = mrow + mi*16 + (lane >> 2);
            int col = ncol + ni*8 + (lane & 3) * 2;
            float* c = &acc[(mi*8+ni)*4];
            Ts[row * TSTR + col]           = c[0];
            Ts[row * TSTR + col + 1]       = c[1];
            Ts[(row + 8) * TSTR + col]     = c[2];
            Ts[(row + 8) * TSTR + col + 1] = c[3];
        }
    __syncthreads();

    const float* adjb = adj + (size_t)b * NN * NN;
    float* Pb = g_P + (size_t)b * NN * NN;
    const int a = tid >> 5, c4 = tid & 31;

    float cs[4] = {0.f, 0.f, 0.f, 0.f};
#pragma unroll
    for (int it = 0; it < 16; it++) {
        int rr = a + 8 * it;
        int jg = jT * 128 + rr, kg = kT * 128 + 4 * c4;
        float4 av = *(const float4*)&adjb[(size_t)jg * NN + kg];
        const float* tr = &Ts[rr * TSTR + 4 * c4];
        float4 pv;
        pv.x = (av.x > 0.f) ? __expf(tr[0]) : -1.f;
        pv.y = (av.y > 0.f) ? __expf(tr[1]) : -1.f;
        pv.z = (av.z > 0.f) ? __expf(tr[2]) : -1.f;
        pv.w = (av.w > 0.f) ? __expf(tr[3]) : -1.f;
        *(float4*)&Pb[(size_t)jg * NN + kg] = pv;
        cs[0] += fabsf(pv.x); cs[1] += fabsf(pv.y);
        cs[2] += fabsf(pv.z); cs[3] += fabsf(pv.w);
    }
    *(float4*)&red[a * 128 + 4 * c4] = make_float4(cs[0], cs[1], cs[2], cs[3]);
    __syncthreads();
    if (tid < 128) {
        float s = 0.f;
#pragma unroll
        for (int q = 0; q < 8; q++) s += red[q * 128 + tid];
        g_dpart[(b * 8 + jT) * NN + kT * 128 + tid] = s;
    }
    __syncthreads();

    if (jT != kT) {
        float cs2[4] = {0.f, 0.f, 0.f, 0.f};
#pragma unroll
        for (int it = 0; it < 16; it++) {
            int rr = a + 8 * it;
            int kg = kT * 128 + rr, jg = jT * 128 + 4 * c4;
            float4 av = *(const float4*)&adjb[(size_t)kg * NN + jg];
            float e0 = Ts[(4*c4+0) * TSTR + rr];
            float e1 = Ts[(4*c4+1) * TSTR + rr];
            float e2 = Ts[(4*c4+2) * TSTR + rr];
            float e3 = Ts[(4*c4+3) * TSTR + rr];
            float4 pv;
            pv.x = (av.x > 0.f) ? __expf(e0) : -1.f;
            pv.y = (av.y > 0.f) ? __expf(e1) : -1.f;
            pv.z = (av.z > 0.f) ? __expf(e2) : -1.f;
            pv.w = (av.w > 0.f) ? __expf(e3) : -1.f;
            *(float4*)&Pb[(size_t)kg * NN + jg] = pv;
            cs2[0] += fabsf(pv.x); cs2[1] += fabsf(pv.y);
            cs2[2] += fabsf(pv.z); cs2[3] += fabsf(pv.w);
        }
        __syncthreads();
        *(float4*)&red[a * 128 + 4 * c4] = make_float4(cs2[0], cs2[1], cs2[2], cs2[3]);
        __syncthreads();
        if (tid < 128) {
            float s = 0.f;
#pragma unroll
            for (int q = 0; q < 8; q++) s += red[q * 128 + tid];
            g_dpart[(b * 8 + kT) * NN + jT * 128 + tid] = s;
        }
    }
}

// ---------------------------------------------------------------------------
// K4: combine 8 partials -> rden
// ---------------------------------------------------------------------------
__global__ void den_comb_kernel() {
    const int b = blockIdx.y;
    const int col = blockIdx.x * 512 + threadIdx.x;
    float s = 0.f;
#pragma unroll
    for (int seg = 0; seg < 8; seg++)
        s += g_dpart[(b * 8 + seg) * NN + col];
    g_rden[b * NN + col] = 1.0f / s;
}

// ---------------------------------------------------------------------------
// K5: aggregation, M=64 tiles, single-buffer, 2 CTA/SM. grid (16 iT, 16 b).
// A bufs 64xLDO (a1,a2), B bufs 128xLDO (b1,b2). 55296 B smem.
// ---------------------------------------------------------------------------
#define AG_A1 0
#define AG_A2 MATB64
#define AG_B1 (2*MATB64)
#define AG_B2 (2*MATB64 + MATB)
#define AG_SMEM (2*MATB64 + 2*MATB)   // 55296

__global__ void __launch_bounds__(256, 2)
agg_mma_kernel(const float* __restrict__ x,
               const float* __restrict__ wiu, const float* __restrict__ wix,
               const float* __restrict__ wfu, const float* __restrict__ wfx,
               const float* __restrict__ wou, const float* __restrict__ wox,
               float* __restrict__ out) {
    extern __shared__ char smem[];
    const uint32_t sb = smem_u32(smem);
    const int tid = threadIdx.x;
    const int wid = tid >> 5, lane = tid & 31;
    const int b = blockIdx.y;
    const int i0 = blockIdx.x * 64;
    const int mrow = (wid >> 2) * 32, ncol = (wid & 3) * 32;
    const int lg = lane >> 3, lr = lane & 7;

    float acc[32];
#pragma unroll
    for (int i = 0; i < 32; i++) acc[i] = 0.f;

    for (int c = 0; c < 16; c++) {
        const int j0 = c * 64;
        if (c) __syncthreads();
        // B (hT splits) via cp.async
#pragma unroll
        for (int it = 0; it < 4; it++) {
            int row = it * 32 + (tid >> 3), f8 = tid & 7;
            size_t so = ((size_t)(b * DD + row)) * NN + j0 + f8 * 8;
            uint32_t off = row * (LDO*2) + f8 * 16;
            CP_ASYNC16(sb + AG_B1 + off, (const void*)&g_hT1[so]);
            CP_ASYNC16(sb + AG_B2 + off, (const void*)&g_hT2[so]);
        }
        CP_COMMIT();
        // attn: P -> max(,0)*rden -> bf16 split -> STS (overlaps with cp.async)
        {
            char* a1c = smem + AG_A1;
            char* a2c = smem + AG_A2;
#pragma unroll
            for (int it = 0; it < 4; it++) {
                int u = tid + it * 256;
                int row = u >> 4, q = u & 15;
                float4 pv = *(const float4*)&g_P[((size_t)(b * NN + i0 + row)) * NN + j0 + 4 * q];
                float4 rd = *(const float4*)&g_rden[b * NN + j0 + 4 * q];
                float av[4];
                av[0] = fmaxf(pv.x, 0.f) * rd.x;
                av[1] = fmaxf(pv.y, 0.f) * rd.y;
                av[2] = fmaxf(pv.z, 0.f) * rd.z;
                av[3] = fmaxf(pv.w, 0.f) * rd.w;
                __nv_bfloat16 v1[4], v2[4];
#pragma unroll
                for (int i = 0; i < 4; i++) split2(av[i], v1[i], v2[i]);
                uint32_t off = row * (LDO*2) + q * 8;
                *(uint2*)(a1c + off) = *(uint2*)v1;
                *(uint2*)(a2c + off) = *(uint2*)v2;
            }
        }
        CP_WAIT0();
        __syncthreads();
        // mma: fragment-reuse, M=64 (mi<2), N=32 per warp (nb<2, ni<4)
#pragma unroll
        for (int ks = 0; ks < 4; ks++) {
            const int kk = ks * 16;
            uint32_t a1f[2][4], a2f[2][4];
#pragma unroll
            for (int mi = 0; mi < 2; mi++) {
                uint32_t ro = ((mrow + mi*16 + (lane & 15)) * LDO + kk + (lane >> 4) * 8) * 2;
                ldsm4(a1f[mi], sb + AG_A1 + ro);
                ldsm4(a2f[mi], sb + AG_A2 + ro);
            }
            uint32_t bf[2][4];
#pragma unroll
            for (int nb = 0; nb < 2; nb++) {
                int n = ncol + nb * 16 + (lg >> 1) * 8 + lr;
                ldsm4(bf[nb], sb + AG_B1 + (n * LDO + kk + (lg & 1) * 8) * 2);
            }
#pragma unroll
            for (int mi = 0; mi < 2; mi++)
#pragma unroll
                for (int ni = 0; ni < 4; ni++) {
                    mma16816(&acc[(mi*4+ni)*4], a1f[mi], &bf[ni>>1][(ni&1)*2]);
                    mma16816(&acc[(mi*4+ni)*4], a2f[mi], &bf[ni>>1][(ni&1)*2]);
                }
#pragma unroll
            for (int nb = 0; nb < 2; nb++) {
                int n = ncol + nb * 16 + (lg >> 1) * 8 + lr;
                ldsm4(bf[nb], sb + AG_B2 + (n * LDO + kk + (lg & 1) * 8) * 2);
            }
#pragma unroll
            for (int mi = 0; mi < 2; mi++)
#pragma unroll
                for (int ni = 0; ni < 4; ni++)
                    mma16816(&acc[(mi*4+ni)*4], a1f[mi], &bf[ni>>1][(ni&1)*2]);
        }
    }

    // h' = relu(acc) -> hp [64][132]
    __syncthreads();
    float* hp = (float*)smem;
#pragma unroll
    for (int mi = 0; mi < 2; mi++)
#pragma unroll
        for (int ni = 0; ni < 4; ni++) {
            int row = mrow + mi*16 + (lane >> 2);
            int col = ncol + ni*8 + (lane & 3) * 2;
            float* cc = &acc[(mi*4+ni)*4];
            hp[row * 132 + col]         = fmaxf(cc[0], 0.f);
            hp[row * 132 + col + 1]     = fmaxf(cc[1], 0.f);
            hp[(row+8) * 132 + col]     = fmaxf(cc[2], 0.f);
            hp[(row+8) * 132 + col + 1] = fmaxf(cc[3], 0.f);
        }
    __syncthreads();

    float4 ui = *(const float4*)&wiu[lane * 4];
    float4 xi = *(const float4*)&wix[lane * 4];
    float4 uf = *(const float4*)&wfu[lane * 4];
    float4 xf = *(const float4*)&wfx[lane * 4];
    float4 uo = *(const float4*)&wou[lane * 4];
    float4 xo = *(const float4*)&wox[lane * 4];

    for (int r = wid; r < 64; r += 8) {
        size_t n = (size_t)b * NN + i0 + r;
        float4 h4 = *(const float4*)&hp[r * 132 + lane * 4];
        float4 x4 = *(const float4*)&x[n * DD + lane * 4];
        float zi = h4.x*ui.x + h4.y*ui.y + h4.z*ui.z + h4.w*ui.w
                 + x4.x*xi.x + x4.y*xi.y + x4.z*xi.z + x4.w*xi.w;
        float zf = h4.x*uf.x + h4.y*uf.y + h4.z*uf.z + h4.w*uf.w
                 + x4.x*xf.x + x4.y*xf.y + x4.z*xf.z + x4.w*xf.w;
        float zo = h4.x*uo.x + h4.y*uo.y + h4.z*uo.z + h4.w*uo.w
                 + x4.x*xo.x + x4.y*xo.y + x4.z*xo.z + x4.w*xo.w;
#pragma unroll
        for (int off = 16; off; off >>= 1) {
            zi += __shfl_xor_sync(0xffffffffu, zi, off);
            zf += __shfl_xor_sync(0xffffffffu, zf, off);
            zo += __shfl_xor_sync(0xffffffffu, zo, off);
        }
        float ic = 1.f / (1.f + expf(-zi));
        float fc = 1.f / (1.f + expf(-zf));
        float oc = 1.f / (1.f + expf(-zo));
        float4 o;
        o.x = oc * tanhf(ic * h4.x + fc * x4.x);
        o.y = oc * tanhf(ic * h4.y + fc * x4.y);
        o.z = oc * tanhf(ic * h4.z + fc * x4.z);
        o.w = oc * tanhf(ic * h4.w + fc * x4.w);
        *(float4*)&out[n * DD + lane * 4] = o;
    }
}

// ---------------------------------------------------------------------------
extern "C" void kernel_launch(void* const* d_in, const int* in_sizes, int n_in,
                              void* d_out, int out_size) {
    const float* x   = (const float*)d_in[0];
    const float* adj = (const float*)d_in[1];
    const float* Ww  = (const float*)d_in[2];
    const float* Wb  = (const float*)d_in[3];
    const float* A   = (const float*)d_in[4];
    const float* wiu = (const float*)d_in[5];
    const float* wix = (const float*)d_in[6];
    const float* wfu = (const float*)d_in[7];
    const float* wfx = (const float*)d_in[8];
    const float* wou = (const float*)d_in[9];
    const float* wox = (const float*)d_in[10];
    float* out = (float*)d_out;

    cudaFuncSetAttribute((const void*)gemmht_kernel,
                         cudaFuncAttributeMaxDynamicSharedMemorySize, 131072);
    cudaFuncSetAttribute((const void*)scores_mma_kernel,
                         cudaFuncAttributeMaxDynamicSharedMemorySize, SC_SMEM);
    cudaFuncSetAttribute((const void*)agg_mma_kernel,
                         cudaFuncAttributeMaxDynamicSharedMemorySize, AG_SMEM);

    prep_M2_kernel<<<16, 256>>>(Ww, Wb, A);
    gemmht_kernel<<<dim3(128, 2), 256, 131072>>>(x, Ww, Wb);
    scores_mma_kernel<<<dim3(36, 16), 256, SC_SMEM>>>(adj);
    den_comb_kernel<<<dim3(2, 16), 512>>>();
    agg_mma_kernel<<<dim3(16, 16), 256, AG_SMEM>>>(x, wiu, wix, wfu, wfx, wou, wox, out);
}